// round 15
// baseline (speedup 1.0000x reference)
#include <cuda_runtime.h>

// Problem constants
#define BB   256
#define TT   2048
#define INP  64
#define HH   32
#define NCLS 5

// ---------------- scratch (no dynamic alloc allowed) ----------------
__device__ float d_GX[(size_t)BB * TT * 128];  // W_ih[:, :64]@x_t + b_ih + b_hh, layout [b*T+t][128]
__device__ float d_P[128 * NCLS];              // W_ih[:, 64:] @ emb[n]^T per gate-row

// Packed 2-wide fp32 FMA (Blackwell FFMA2 via PTX fma.rn.f32x2)
__device__ __forceinline__ unsigned long long fma2(unsigned long long a,
                                                   unsigned long long b,
                                                   unsigned long long c) {
    unsigned long long d;
    asm("fma.rn.f32x2 %0, %1, %2, %3;" : "=l"(d) : "l"(a), "l"(b), "l"(c));
    return d;
}
__device__ __forceinline__ float2 unpack2(unsigned long long v) {
    float2 r;
    asm("mov.b64 {%0, %1}, %2;" : "=f"(r.x), "=f"(r.y) : "l"(v));
    return r;
}
__device__ __forceinline__ float sel5(int a, float f0, float f1, float f2, float f3, float f4) {
    float r = f0;
    r = (a == 1) ? f1 : r;
    r = (a == 2) ? f2 : r;
    r = (a == 3) ? f3 : r;
    r = (a == 4) ? f4 : r;
    return r;
}
// Fast-but-tight activations: MUFU.EX2 + MUFU.RCP paths, rel err ~2^-21
__device__ __forceinline__ float fsigmoid(float x) {
    return __fdividef(1.0f, 1.0f + __expf(-x));
}
__device__ __forceinline__ float ftanh_tight(float x) {
    return __fdividef(2.0f, 1.0f + __expf(-2.0f * x)) - 1.0f;
}

// ---------------- prepass 1: P[r][n] = W_ih[r, 64:128] . emb[n] ----------------
__global__ void p_kernel(const float* __restrict__ Wih, const float* __restrict__ emb) {
    int r = threadIdx.x;  // 0..127
    #pragma unroll
    for (int n = 0; n < NCLS; n++) {
        float a = 0.f;
        #pragma unroll
        for (int k = 0; k < INP; k++)
            a += Wih[r * 128 + 64 + k] * emb[n * INP + k];
        d_P[r * NCLS + n] = a;
    }
}

// ---------------- prepass 2: GX = x @ W_ih[:, :64]^T + (b_ih + b_hh) ----------------
#define GX_CHUNK 64
__global__ void __launch_bounds__(128) gx_kernel(
    const float* __restrict__ x, const float* __restrict__ Wih,
    const float* __restrict__ bih, const float* __restrict__ bhh)
{
    const int r = threadIdx.x;  // gate row 0..127
    const size_t base = (size_t)blockIdx.x * GX_CHUNK;  // first bt of this CTA

    // W_ih row r, columns 0..63 (x part) as 32 packed pairs
    unsigned long long w[32];
    {
        const ulonglong2* p = reinterpret_cast<const ulonglong2*>(Wih + r * 128);
        #pragma unroll
        for (int i = 0; i < 16; i++) {
            ulonglong2 u = p[i];
            w[2 * i] = u.x; w[2 * i + 1] = u.y;
        }
    }
    const float br = bih[r] + bhh[r];

    __shared__ __align__(16) float sx[2][INP];

    // preload bt = base
    if (r < 16)
        reinterpret_cast<float4*>(sx[0])[r] =
            reinterpret_cast<const float4*>(x + base * INP)[r];
    __syncthreads();

    #pragma unroll 1
    for (int p = 0; p < GX_CHUNK; p++) {
        // load next bt into the other buffer (no sync needed before compute of current)
        if (r < 16 && (p + 1) < GX_CHUNK)
            reinterpret_cast<float4*>(sx[(p + 1) & 1])[r] =
                reinterpret_cast<const float4*>(x + (base + p + 1) * INP)[r];

        const ulonglong2* v2 = reinterpret_cast<const ulonglong2*>(sx[p & 1]);
        unsigned long long a0 = 0ull, a1 = 0ull, a2 = 0ull, a3 = 0ull;
        #pragma unroll
        for (int m = 0; m < 16; m++) {
            ulonglong2 u = v2[m];
            if (m & 1) { a2 = fma2(w[2 * m], u.x, a2); a3 = fma2(w[2 * m + 1], u.y, a3); }
            else       { a0 = fma2(w[2 * m], u.x, a0); a1 = fma2(w[2 * m + 1], u.y, a1); }
        }
        float2 f0 = unpack2(a0), f1 = unpack2(a1), f2 = unpack2(a2), f3 = unpack2(a3);
        d_GX[(base + p) * 128 + r] = br + ((f0.x + f0.y) + (f1.x + f1.y))
                                        + ((f2.x + f2.y) + (f3.x + f3.y));
        __syncthreads();  // protect buffer reuse two iterations out
    }
}

// ---------------- recurrent kernel: one warp per batch row, no __syncthreads ----------------
// Lane j owns hidden unit j: gate rows j (i), 32+j (f), 64+j (g), 96+j (o).
// c and h live in-lane; h broadcast via per-warp 32-float SMEM + __syncwarp.
__global__ void __launch_bounds__(64, 1) ar_rec_kernel(
    const float* __restrict__ Whh,  // [128, 32]
    const float* __restrict__ Wfc,  // [5, 32]
    const float* __restrict__ bfc,  // [5]
    float* __restrict__ out)        // [B, T, 5]
{
    const int w = threadIdx.x >> 5;
    const int j = threadIdx.x & 31;
    const int b = blockIdx.x * 2 + w;

    __shared__ __align__(16) float s_h[2][32];

    // W_hh rows for the 4 gates of unit j, packed pairs
    unsigned long long wh[4][16];
    #pragma unroll
    for (int g = 0; g < 4; g++) {
        const ulonglong2* q = reinterpret_cast<const ulonglong2*>(Whh + (g * 32 + j) * HH);
        #pragma unroll
        for (int i = 0; i < 8; i++) {
            ulonglong2 u = q[i];
            wh[g][2 * i] = u.x; wh[g][2 * i + 1] = u.y;
        }
    }
    float wfc_[NCLS], bf[NCLS];
    #pragma unroll
    for (int n = 0; n < NCLS; n++) { wfc_[n] = Wfc[n * HH + j]; bf[n] = bfc[n]; }

    // P columns for this lane's 4 gate rows
    float Pg[4][NCLS];
    #pragma unroll
    for (int g = 0; g < 4; g++)
        #pragma unroll
        for (int n = 0; n < NCLS; n++)
            Pg[g][n] = d_P[(g * 32 + j) * NCLS + n];

    float c = 0.f, h = 0.f;
    s_h[w][j] = 0.f;
    __syncwarp();

    const float* gxp = d_GX + (size_t)b * TT * 128;
    // prefetch pipeline, distance 2
    float gx_c[4], gx_n1[4], gx_n2[4];
    #pragma unroll
    for (int g = 0; g < 4; g++) {
        gx_c[g]  = __ldg(gxp + g * 32 + j);
        gx_n1[g] = __ldg(gxp + 128 + g * 32 + j);
    }

    float* op = out + (size_t)b * TT * NCLS;

    #pragma unroll 1
    for (int t = 0; t < TT; t++) {
        // prefetch GX for t+2 (two-step slack covers DRAM/L2 latency)
        const int tp = (t + 2 < TT) ? t + 2 : TT - 1;
        #pragma unroll
        for (int g = 0; g < 4; g++)
            gx_n2[g] = __ldg(gxp + (size_t)tp * 128 + g * 32 + j);

        // ---- W_hh . h(t-1): 4 gate dots, packed, weights in registers ----
        const ulonglong2* hv = reinterpret_cast<const ulonglong2*>(s_h[w]);
        unsigned long long a0[4] = {0ull, 0ull, 0ull, 0ull};
        unsigned long long a1[4] = {0ull, 0ull, 0ull, 0ull};
        #pragma unroll
        for (int m = 0; m < 8; m++) {
            ulonglong2 u = hv[m];  // broadcast LDS.128
            #pragma unroll
            for (int g = 0; g < 4; g++) a0[g] = fma2(wh[g][2 * m],     u.x, a0[g]);
            #pragma unroll
            for (int g = 0; g < 4; g++) a1[g] = fma2(wh[g][2 * m + 1], u.y, a1[g]);
        }

        // ---- logits(t-1) butterfly on h register (overlaps with dot) ----
        float p0 = wfc_[0] * h, p1 = wfc_[1] * h, p2 = wfc_[2] * h,
              p3 = wfc_[3] * h, p4 = wfc_[4] * h;
        #pragma unroll
        for (int off = 16; off > 0; off >>= 1) {
            p0 += __shfl_xor_sync(0xffffffffu, p0, off);
            p1 += __shfl_xor_sync(0xffffffffu, p1, off);
            p2 += __shfl_xor_sync(0xffffffffu, p2, off);
            p3 += __shfl_xor_sync(0xffffffffu, p3, off);
            p4 += __shfl_xor_sync(0xffffffffu, p4, off);
        }
        p0 += bf[0]; p1 += bf[1]; p2 += bf[2]; p3 += bf[3]; p4 += bf[4];

        // argmax (first-max tie-break, matching jnp.argmax)
        int amax = 0; float best = p0;
        if (p1 > best) { best = p1; amax = 1; }
        if (p2 > best) { best = p2; amax = 2; }
        if (p3 > best) { best = p3; amax = 3; }
        if (p4 > best) { best = p4; amax = 4; }

        // output for step t-1 (off the critical path; fast intrinsics, argmax unaffected)
        if (t > 0) {
            float e0 = __expf(p0 - best), e1 = __expf(p1 - best), e2 = __expf(p2 - best),
                  e3 = __expf(p3 - best), e4 = __expf(p4 - best);
            float lse = best + __logf(e0 + e1 + e2 + e3 + e4);
            if (j < NCLS)
                op[(size_t)(t - 1) * NCLS + j] = sel5(j, p0, p1, p2, p3, p4) - lse;
        }

        // ---- raw gates: gx + P[:, amax(t-1)] + Whh.h ----
        const float pm = (t > 0) ? 1.f : 0.f;  // prev(-1) = 0
        float raw[4];
        #pragma unroll
        for (int g = 0; g < 4; g++) {
            float2 f0 = unpack2(a0[g]), f1 = unpack2(a1[g]);
            float psel = sel5(amax, Pg[g][0], Pg[g][1], Pg[g][2], Pg[g][3], Pg[g][4]);
            raw[g] = gx_c[g] + pm * psel + ((f0.x + f0.y) + (f1.x + f1.y));
        }

        // ---- LSTM update: tight MUFU-based activations (rel err ~2^-21) ----
        float iv = fsigmoid(raw[0]);
        float fv = fsigmoid(raw[1]);
        float gv = ftanh_tight(raw[2]);
        float ov = fsigmoid(raw[3]);
        c = fv * c + iv * gv;
        h = ov * ftanh_tight(c);

        __syncwarp();
        s_h[w][j] = h;
        __syncwarp();

        #pragma unroll
        for (int g = 0; g < 4; g++) { gx_c[g] = gx_n1[g]; gx_n1[g] = gx_n2[g]; }
    }

    // final logits for t = TT-1
    {
        float p0 = wfc_[0] * h, p1 = wfc_[1] * h, p2 = wfc_[2] * h,
              p3 = wfc_[3] * h, p4 = wfc_[4] * h;
        #pragma unroll
        for (int off = 16; off > 0; off >>= 1) {
            p0 += __shfl_xor_sync(0xffffffffu, p0, off);
            p1 += __shfl_xor_sync(0xffffffffu, p1, off);
            p2 += __shfl_xor_sync(0xffffffffu, p2, off);
            p3 += __shfl_xor_sync(0xffffffffu, p3, off);
            p4 += __shfl_xor_sync(0xffffffffu, p4, off);
        }
        p0 += bf[0]; p1 += bf[1]; p2 += bf[2]; p3 += bf[3]; p4 += bf[4];
        float best = fmaxf(fmaxf(fmaxf(p0, p1), fmaxf(p2, p3)), p4);
        float e0 = __expf(p0 - best), e1 = __expf(p1 - best), e2 = __expf(p2 - best),
              e3 = __expf(p3 - best), e4 = __expf(p4 - best);
        float lse = best + __logf(e0 + e1 + e2 + e3 + e4);
        if (j < NCLS)
            op[(size_t)(TT - 1) * NCLS + j] = sel5(j, p0, p1, p2, p3, p4) - lse;
    }
}

extern "C" void kernel_launch(void* const* d_in, const int* in_sizes, int n_in,
                              void* d_out, int out_size) {
    // metadata order: x, x_lengths, edge_list, W_ih, W_hh, b_ih, b_hh, W_fc, b_fc, emb
    const float* x   = (const float*)d_in[0];
    const float* Wih = (const float*)d_in[3];
    const float* Whh = (const float*)d_in[4];
    const float* bih = (const float*)d_in[5];
    const float* bhh = (const float*)d_in[6];
    const float* Wfc = (const float*)d_in[7];
    const float* bfc = (const float*)d_in[8];
    const float* emb = (const float*)d_in[9];
    float* out = (float*)d_out;

    p_kernel<<<1, 128>>>(Wih, emb);
    gx_kernel<<<(BB * TT) / GX_CHUNK, 128>>>(x, Wih, bih, bhh);
    ar_rec_kernel<<<BB / 2, 64>>>(Whh, Wfc, bfc, out);
}

// round 16
// speedup vs baseline: 1.0219x; 1.0219x over previous
#include <cuda_runtime.h>

// Problem constants
#define BB   256
#define TT   2048
#define INP  64
#define HH   32
#define NCLS 5

// ---------------- scratch (no dynamic alloc allowed) ----------------
__device__ float d_GX[(size_t)BB * TT * 128];  // W_ih[:, :64]@x_t + b_ih + b_hh, layout [b*T+t][128]
__device__ float d_P[128 * NCLS];              // W_ih[:, 64:] @ emb[n]^T per gate-row

// Packed 2-wide fp32 FMA (Blackwell FFMA2 via PTX fma.rn.f32x2)
__device__ __forceinline__ unsigned long long fma2(unsigned long long a,
                                                   unsigned long long b,
                                                   unsigned long long c) {
    unsigned long long d;
    asm("fma.rn.f32x2 %0, %1, %2, %3;" : "=l"(d) : "l"(a), "l"(b), "l"(c));
    return d;
}
__device__ __forceinline__ float2 unpack2(unsigned long long v) {
    float2 r;
    asm("mov.b64 {%0, %1}, %2;" : "=f"(r.x), "=f"(r.y) : "l"(v));
    return r;
}
__device__ __forceinline__ float sel5(int a, float f0, float f1, float f2, float f3, float f4) {
    float r = f0;
    r = (a == 1) ? f1 : r;
    r = (a == 2) ? f2 : r;
    r = (a == 3) ? f3 : r;
    r = (a == 4) ? f4 : r;
    return r;
}
// Fast-but-tight activations: MUFU.EX2 + MUFU.RCP paths, rel err ~2^-21
__device__ __forceinline__ float fsigmoid(float x) {
    return __fdividef(1.0f, 1.0f + __expf(-x));
}
__device__ __forceinline__ float ftanh_tight(float x) {
    return __fdividef(2.0f, 1.0f + __expf(-2.0f * x)) - 1.0f;
}

// ---------------- prepass 1: P[r][n] = W_ih[r, 64:128] . emb[n] ----------------
__global__ void p_kernel(const float* __restrict__ Wih, const float* __restrict__ emb) {
    int r = threadIdx.x;  // 0..127
    #pragma unroll
    for (int n = 0; n < NCLS; n++) {
        float a = 0.f;
        #pragma unroll
        for (int k = 0; k < INP; k++)
            a += Wih[r * 128 + 64 + k] * emb[n * INP + k];
        d_P[r * NCLS + n] = a;
    }
}

// ---------------- prepass 2: GX = x @ W_ih[:, :64]^T + (b_ih + b_hh) ----------------
#define GX_CHUNK 64
__global__ void __launch_bounds__(128) gx_kernel(
    const float* __restrict__ x, const float* __restrict__ Wih,
    const float* __restrict__ bih, const float* __restrict__ bhh)
{
    const int r = threadIdx.x;  // gate row 0..127
    const size_t base = (size_t)blockIdx.x * GX_CHUNK;  // first bt of this CTA

    // W_ih row r, columns 0..63 (x part) as 32 packed pairs
    unsigned long long w[32];
    {
        const ulonglong2* p = reinterpret_cast<const ulonglong2*>(Wih + r * 128);
        #pragma unroll
        for (int i = 0; i < 16; i++) {
            ulonglong2 u = p[i];
            w[2 * i] = u.x; w[2 * i + 1] = u.y;
        }
    }
    const float br = bih[r] + bhh[r];

    __shared__ __align__(16) float sx[2][INP];

    // preload bt = base
    if (r < 16)
        reinterpret_cast<float4*>(sx[0])[r] =
            reinterpret_cast<const float4*>(x + base * INP)[r];
    __syncthreads();

    #pragma unroll 1
    for (int p = 0; p < GX_CHUNK; p++) {
        // load next bt into the other buffer (no sync needed before compute of current)
        if (r < 16 && (p + 1) < GX_CHUNK)
            reinterpret_cast<float4*>(sx[(p + 1) & 1])[r] =
                reinterpret_cast<const float4*>(x + (base + p + 1) * INP)[r];

        const ulonglong2* v2 = reinterpret_cast<const ulonglong2*>(sx[p & 1]);
        unsigned long long a0 = 0ull, a1 = 0ull, a2 = 0ull, a3 = 0ull;
        #pragma unroll
        for (int m = 0; m < 16; m++) {
            ulonglong2 u = v2[m];
            if (m & 1) { a2 = fma2(w[2 * m], u.x, a2); a3 = fma2(w[2 * m + 1], u.y, a3); }
            else       { a0 = fma2(w[2 * m], u.x, a0); a1 = fma2(w[2 * m + 1], u.y, a1); }
        }
        float2 f0 = unpack2(a0), f1 = unpack2(a1), f2 = unpack2(a2), f3 = unpack2(a3);
        d_GX[(base + p) * 128 + r] = br + ((f0.x + f0.y) + (f1.x + f1.y))
                                        + ((f2.x + f2.y) + (f3.x + f3.y));
        __syncthreads();  // protect buffer reuse two iterations out
    }
}

// ---------------- recurrent kernel: one warp per batch row, no __syncthreads ----------------
// Lane j owns hidden unit j: gate rows j (i), 32+j (f), 64+j (g), 96+j (o).
// c and h live in-lane; h broadcast via per-warp 32-float SMEM + __syncwarp.
__global__ void __launch_bounds__(64, 1) ar_rec_kernel(
    const float* __restrict__ Whh,  // [128, 32]
    const float* __restrict__ Wfc,  // [5, 32]
    const float* __restrict__ bfc,  // [5]
    float* __restrict__ out)        // [B, T, 5]
{
    const int w = threadIdx.x >> 5;
    const int j = threadIdx.x & 31;
    const int b = blockIdx.x * 2 + w;

    __shared__ __align__(16) float s_h[2][32];

    // W_hh rows for the 4 gates of unit j, packed pairs
    unsigned long long wh[4][16];
    #pragma unroll
    for (int g = 0; g < 4; g++) {
        const ulonglong2* q = reinterpret_cast<const ulonglong2*>(Whh + (g * 32 + j) * HH);
        #pragma unroll
        for (int i = 0; i < 8; i++) {
            ulonglong2 u = q[i];
            wh[g][2 * i] = u.x; wh[g][2 * i + 1] = u.y;
        }
    }
    float wfc_[NCLS], bf[NCLS];
    #pragma unroll
    for (int n = 0; n < NCLS; n++) { wfc_[n] = Wfc[n * HH + j]; bf[n] = bfc[n]; }

    // P columns for this lane's 4 gate rows
    float Pg[4][NCLS];
    #pragma unroll
    for (int g = 0; g < 4; g++)
        #pragma unroll
        for (int n = 0; n < NCLS; n++)
            Pg[g][n] = d_P[(g * 32 + j) * NCLS + n];

    float c = 0.f, h = 0.f;
    s_h[w][j] = 0.f;
    __syncwarp();

    const float* gxp = d_GX + (size_t)b * TT * 128;
    // prefetch pipeline, distance 2
    float gx_c[4], gx_n1[4], gx_n2[4];
    #pragma unroll
    for (int g = 0; g < 4; g++) {
        gx_c[g]  = __ldg(gxp + g * 32 + j);
        gx_n1[g] = __ldg(gxp + 128 + g * 32 + j);
    }

    float* op = out + (size_t)b * TT * NCLS;

    #pragma unroll 1
    for (int t = 0; t < TT; t++) {
        // prefetch GX for t+2 (two-step slack covers DRAM/L2 latency)
        const int tp = (t + 2 < TT) ? t + 2 : TT - 1;
        #pragma unroll
        for (int g = 0; g < 4; g++)
            gx_n2[g] = __ldg(gxp + (size_t)tp * 128 + g * 32 + j);

        // ---- W_hh . h(t-1): 4 gate dots, packed, weights in registers ----
        const ulonglong2* hv = reinterpret_cast<const ulonglong2*>(s_h[w]);
        unsigned long long a0[4] = {0ull, 0ull, 0ull, 0ull};
        unsigned long long a1[4] = {0ull, 0ull, 0ull, 0ull};
        #pragma unroll
        for (int m = 0; m < 8; m++) {
            ulonglong2 u = hv[m];  // broadcast LDS.128
            #pragma unroll
            for (int g = 0; g < 4; g++) a0[g] = fma2(wh[g][2 * m],     u.x, a0[g]);
            #pragma unroll
            for (int g = 0; g < 4; g++) a1[g] = fma2(wh[g][2 * m + 1], u.y, a1[g]);
        }

        // ---- logits(t-1) butterfly on h register (overlaps with dot) ----
        float p0 = wfc_[0] * h, p1 = wfc_[1] * h, p2 = wfc_[2] * h,
              p3 = wfc_[3] * h, p4 = wfc_[4] * h;
        #pragma unroll
        for (int off = 16; off > 0; off >>= 1) {
            p0 += __shfl_xor_sync(0xffffffffu, p0, off);
            p1 += __shfl_xor_sync(0xffffffffu, p1, off);
            p2 += __shfl_xor_sync(0xffffffffu, p2, off);
            p3 += __shfl_xor_sync(0xffffffffu, p3, off);
            p4 += __shfl_xor_sync(0xffffffffu, p4, off);
        }
        p0 += bf[0]; p1 += bf[1]; p2 += bf[2]; p3 += bf[3]; p4 += bf[4];

        // argmax (first-max tie-break, matching jnp.argmax)
        int amax = 0; float best = p0;
        if (p1 > best) { best = p1; amax = 1; }
        if (p2 > best) { best = p2; amax = 2; }
        if (p3 > best) { best = p3; amax = 3; }
        if (p4 > best) { best = p4; amax = 4; }

        // output for step t-1 (off the critical path; fast intrinsics, argmax unaffected)
        if (t > 0) {
            float e0 = __expf(p0 - best), e1 = __expf(p1 - best), e2 = __expf(p2 - best),
                  e3 = __expf(p3 - best), e4 = __expf(p4 - best);
            float lse = best + __logf(e0 + e1 + e2 + e3 + e4);
            if (j < NCLS)
                op[(size_t)(t - 1) * NCLS + j] = sel5(j, p0, p1, p2, p3, p4) - lse;
        }

        // ---- raw gates: gx + P[:, amax(t-1)] + Whh.h ----
        const float pm = (t > 0) ? 1.f : 0.f;  // prev(-1) = 0
        float raw[4];
        #pragma unroll
        for (int g = 0; g < 4; g++) {
            float2 f0 = unpack2(a0[g]), f1 = unpack2(a1[g]);
            float psel = sel5(amax, Pg[g][0], Pg[g][1], Pg[g][2], Pg[g][3], Pg[g][4]);
            raw[g] = gx_c[g] + pm * psel + ((f0.x + f0.y) + (f1.x + f1.y));
        }

        // ---- LSTM update: tight MUFU-based activations (rel err ~2^-21) ----
        float iv = fsigmoid(raw[0]);
        float fv = fsigmoid(raw[1]);
        float gv = ftanh_tight(raw[2]);
        float ov = fsigmoid(raw[3]);
        c = fv * c + iv * gv;
        h = ov * ftanh_tight(c);

        __syncwarp();
        s_h[w][j] = h;
        __syncwarp();

        #pragma unroll
        for (int g = 0; g < 4; g++) { gx_c[g] = gx_n1[g]; gx_n1[g] = gx_n2[g]; }
    }

    // final logits for t = TT-1
    {
        float p0 = wfc_[0] * h, p1 = wfc_[1] * h, p2 = wfc_[2] * h,
              p3 = wfc_[3] * h, p4 = wfc_[4] * h;
        #pragma unroll
        for (int off = 16; off > 0; off >>= 1) {
            p0 += __shfl_xor_sync(0xffffffffu, p0, off);
            p1 += __shfl_xor_sync(0xffffffffu, p1, off);
            p2 += __shfl_xor_sync(0xffffffffu, p2, off);
            p3 += __shfl_xor_sync(0xffffffffu, p3, off);
            p4 += __shfl_xor_sync(0xffffffffu, p4, off);
        }
        p0 += bf[0]; p1 += bf[1]; p2 += bf[2]; p3 += bf[3]; p4 += bf[4];
        float best = fmaxf(fmaxf(fmaxf(p0, p1), fmaxf(p2, p3)), p4);
        float e0 = __expf(p0 - best), e1 = __expf(p1 - best), e2 = __expf(p2 - best),
              e3 = __expf(p3 - best), e4 = __expf(p4 - best);
        float lse = best + __logf(e0 + e1 + e2 + e3 + e4);
        if (j < NCLS)
            op[(size_t)(TT - 1) * NCLS + j] = sel5(j, p0, p1, p2, p3, p4) - lse;
    }
}

extern "C" void kernel_launch(void* const* d_in, const int* in_sizes, int n_in,
                              void* d_out, int out_size) {
    // metadata order: x, x_lengths, edge_list, W_ih, W_hh, b_ih, b_hh, W_fc, b_fc, emb
    const float* x   = (const float*)d_in[0];
    const float* Wih = (const float*)d_in[3];
    const float* Whh = (const float*)d_in[4];
    const float* bih = (const float*)d_in[5];
    const float* bhh = (const float*)d_in[6];
    const float* Wfc = (const float*)d_in[7];
    const float* bfc = (const float*)d_in[8];
    const float* emb = (const float*)d_in[9];
    float* out = (float*)d_out;

    p_kernel<<<1, 128>>>(Wih, emb);
    gx_kernel<<<(BB * TT) / GX_CHUNK, 128>>>(x, Wih, bih, bhh);
    ar_rec_kernel<<<BB / 2, 64>>>(Whh, Wfc, bfc, out);
}